// round 14
// baseline (speedup 1.0000x reference)
#include <cuda_runtime.h>
#include <math.h>

#define J   23
#define TPB 256
#define VPB 256
#define PI_F 3.14159265358979323846f

__constant__ int cPAR[J] = {-1,0,1,1,3,4,5,4,7,4,9,1,11,12,13,12,15,12,17,0,19,0,21};

// packed A (69 float4 = 276 floats) + constants (c, ox, oy, oz) at [276..279]
__constant__ __align__(16) float c_pack[280];

typedef unsigned long long u64;

__device__ __forceinline__ void fma2(u64& d, u64 a, u64 b) {
    asm("fma.rn.f32x2 %0, %1, %2, %0;" : "+l"(d) : "l"(a), "l"(b));
}
__device__ __forceinline__ u64 pack2(float v) {
    u64 r;
    asm("mov.b64 %0, {%1, %1};" : "=l"(r) : "f"(v));
    return r;
}
__device__ __forceinline__ void unpack2(u64 v, float& lo, float& hi) {
    asm("mov.b64 {%0, %1}, %2;" : "=f"(lo), "=f"(hi) : "l"(v));
}
__device__ __forceinline__ float tanha(float x) {
    float y;
    asm("tanh.approx.f32 %0, %1;" : "=f"(y) : "f"(x));
    return y;
}
__device__ __forceinline__ unsigned smem_u32(const void* p) {
    return (unsigned)__cvta_generic_to_shared(p);
}

// ---------------- Prep: one warp; writes A + consts into the constant bank, triggers PDL ----------------
__global__ void __launch_bounds__(32) prep_kernel(
    float* __restrict__ cpack,
    const float* __restrict__ jr,
    const float* __restrict__ p0, const float* __restrict__ p1,
    const float* __restrict__ p2, const float* __restrict__ p3,
    const float* __restrict__ p4, const float* __restrict__ p5,
    const float* __restrict__ p12, const float* __restrict__ p13,
    const float* __restrict__ disp, const float* __restrict__ scale,
    const float* __restrict__ loc,
    float* __restrict__ out, int B, int V)
{
    __shared__ float s_Tl[J * 12];
    __shared__ float s_G[J * 12];
    __shared__ float s_pose[J * 3];

    const int tid = threadIdx.x;

    float cst = 0.f, ox = 0.f, oy = 0.f, oz = 0.f;
    if (tid == 31) {
        cst = 0.0035f * scale[0];
        ox = loc[0] + 0.1f * tanha(disp[0]);
        oy = loc[1] + 0.1f * tanha(disp[1]);
        oz = loc[2] + 0.1f * tanha(disp[2]);
        cpack[276] = cst; cpack[277] = ox; cpack[278] = oy; cpack[279] = oz;
    }

    if (tid < J) {
        float fac = 0.f, sy = 1.f, sz = 1.f;
        const float* pp = p0;
        bool has = true;
        switch (tid) {
            case 0:  fac = PI_F / 2.f; pp = p0;  break;
            case 1:  fac = PI_F / 4.f; pp = p1;  break;
            case 2:  fac = PI_F / 9.f; pp = p2;  break;
            case 3:  fac = PI_F / 3.f; pp = p3;  break;
            case 4:  fac = PI_F / 3.f; pp = p4;  break;
            case 5:  fac = PI_F / 3.f; pp = p5;  break;
            case 11: fac = PI_F / 3.f; pp = p3;  sy = -1.f; sz = -1.f; break;
            case 12: fac = PI_F / 3.f; pp = p12; break;
            case 13: fac = PI_F / 3.f; pp = p13; break;
            default: has = false;
        }
        float px = 0.f, py = 0.f, pz = 0.f;
        if (has) {
            px = fac * tanha(pp[0]);
            py = sy * fac * tanha(pp[1]);
            pz = sz * fac * tanha(pp[2]);
        }
        s_pose[3 * tid + 0] = px;
        s_pose[3 * tid + 1] = py;
        s_pose[3 * tid + 2] = pz;

        float ang = sqrtf(px * px + py * py + pz * pz + 1e-12f);
        float inv = 1.f / ang;
        float x = px * inv, y = py * inv, z = pz * inv;
        float s = __sinf(ang), c = __cosf(ang), t = 1.f - c;
        float* T = &s_Tl[tid * 12];
        T[0] = 1.f + t * (-(z * z) - (y * y));
        T[1] = -s * z + t * (x * y);
        T[2] =  s * y + t * (x * z);
        T[4] =  s * z + t * (x * y);
        T[5] = 1.f + t * (-(z * z) - (x * x));
        T[6] = -s * x + t * (y * z);
        T[8] = -s * y + t * (x * z);
        T[9] =  s * x + t * (y * z);
        T[10] = 1.f + t * (-(y * y) - (x * x));

        int par = cPAR[tid];
        float jx = jr[3 * tid], jy = jr[3 * tid + 1], jz = jr[3 * tid + 2];
        if (par >= 0) { jx -= jr[3 * par]; jy -= jr[3 * par + 1]; jz -= jr[3 * par + 2]; }
        T[3] = jx; T[7] = jy; T[11] = jz;
    }
    __syncwarp();

    if (tid < 12) s_G[tid] = s_Tl[tid];
    __syncwarp();
    #pragma unroll
    for (int j = 1; j < J; j++) {
        const int p = cPAR[j];
        if (tid < 12) {
            const int r = tid >> 2, c = tid & 3;
            const float* gp = &s_G[p * 12 + r * 4];
            const float* tl = &s_Tl[j * 12];
            float v = gp[0] * tl[0 * 4 + c]
                    + gp[1] * tl[1 * 4 + c]
                    + gp[2] * tl[2 * 4 + c];
            if (c == 3) v += gp[3];
            s_G[j * 12 + tid] = v;
        }
        __syncwarp();
    }

    if (tid < J) {
        const float* g = &s_G[tid * 12];
        float jx = jr[3 * tid], jy = jr[3 * tid + 1], jz = jr[3 * tid + 2];
        float tcx = g[0] * jx + g[1] * jy + g[2] * jz;
        float tcy = g[4] * jx + g[5] * jy + g[6] * jz;
        float tcz = g[8] * jx + g[9] * jy + g[10] * jz;
        float* a = &cpack[tid * 12];
        a[0] = g[0]; a[1] = g[1]; a[2]  = g[2];  a[3]  = g[3]  - tcx;
        a[4] = g[4]; a[5] = g[5]; a[6]  = g[6];  a[7]  = g[7]  - tcy;
        a[8] = g[8]; a[9] = g[9]; a[10] = g[10]; a[11] = g[11] - tcz;
    }
    __syncwarp();
    __threadfence();
    cudaTriggerProgrammaticLaunchCompletion();

    // small outputs (after trigger; off the lbs critical path)
    const long V3 = 3L * (long)V;
    const long base = (long)B * V3;
    if (tid < J) {
        out[base + 3 * tid + 0] = s_pose[3 * tid + 0];
        out[base + 3 * tid + 1] = s_pose[3 * tid + 1];
        out[base + 3 * tid + 2] = s_pose[3 * tid + 2];
    }
    if (tid == 31) {
        for (int j = 0; j < J; j++) {
            out[base + 69 + 3 * j + 0] = fmaf(cst, s_G[j * 12 + 3],  ox);
            out[base + 69 + 3 * j + 1] = fmaf(cst, s_G[j * 12 + 7],  oy);
            out[base + 69 + 3 * j + 2] = fmaf(cst, s_G[j * 12 + 11], oz);
        }
        out[base + 138] = scale[0];
        out[base + 139] = disp[0];
        out[base + 140] = disp[1];
        out[base + 141] = disp[2];
    }
}

// ---------------- LBS: TMA bulk sk staging, PDL preamble, constant-bank A, f32x2 ----------------
__global__ void __launch_bounds__(TPB, 6) lbs_kernel(
    const float* __restrict__ vt,
    const float* __restrict__ sk,
    const float* __restrict__ la,
    float* __restrict__ out, int V, int B)
{
    __shared__ __align__(16) float s_sk[VPB * 23];
    __shared__ float s_vt[VPB * 3];    // reused for results after compute
    __shared__ float s_la[VPB * 3];
    __shared__ __align__(8) u64 s_mbar;

    const int tid = threadIdx.x;
    const long v0 = (long)blockIdx.x * VPB;
    const int nv  = (V - (int)v0 < VPB) ? (V - (int)v0) : VPB;
    const long V3 = 3L * (long)V;
    const bool full = (nv == VPB);
    const long offLa = (long)B * V3 + 142;

    // ---- PDL preamble (independent of prep) ----
    // 1. TMA bulk copy of the sk tile into smem (single instruction)
    if (tid == 0) {
        const unsigned mb = smem_u32(&s_mbar);
        const unsigned dst = smem_u32(s_sk);
        const unsigned bytes = (unsigned)(nv * 23 * 4);   // multiple of 16
        const void* src = (const void*)(sk + v0 * 23);
        asm volatile("mbarrier.init.shared.b64 [%0], 1;" :: "r"(mb) : "memory");
        asm volatile("mbarrier.arrive.expect_tx.shared.b64 _, [%0], %1;"
                     :: "r"(mb), "r"(bytes) : "memory");
        asm volatile("cp.async.bulk.shared::cta.global.mbarrier::complete_tx::bytes "
                     "[%0], [%1], %2, [%3];"
                     :: "r"(dst), "l"(src), "r"(bytes), "r"(mb) : "memory");
    }

    // 2. vt/la tile loads + la passthrough
    {
        const float4* gv = (const float4*)(vt + v0 * 3);
        const float4* gl = (const float4*)(la + v0 * 3);
        float4* dv = (float4*)s_vt;
        float4* dl = (float4*)s_la;
        float2* gl2 = (float2*)(out + offLa + v0 * 3);
        if (full) {
            if (tid < 192) {
                dv[tid] = __ldcs(gv + tid);
                float4 lq = __ldcs(gl + tid);
                dl[tid] = lq;
                __stcs(gl2 + 2 * tid + 0, make_float2(lq.x, lq.y));
                __stcs(gl2 + 2 * tid + 1, make_float2(lq.z, lq.w));
            }
        } else {
            const int n3 = (nv * 3) >> 2;
            for (int i = tid; i < n3; i += TPB) {
                dv[i] = __ldcs(gv + i);
                float4 lq = __ldcs(gl + i);
                dl[i] = lq;
                __stcs(gl2 + 2 * i + 0, make_float2(lq.x, lq.y));
                __stcs(gl2 + 2 * i + 1, make_float2(lq.z, lq.w));
            }
        }
    }

    cudaGridDependencySynchronize();   // wait for prep's c_pack
    __syncthreads();                   // vt/la smem + mbar init visible

    // wait for the TMA bulk copy
    {
        const unsigned mb = smem_u32(&s_mbar);
        unsigned done;
        asm volatile(
            "{\n\t.reg .pred p;\n\t"
            "mbarrier.try_wait.parity.acquire.cta.shared::cta.b64 p, [%1], 0;\n\t"
            "selp.b32 %0, 1, 0, p;\n\t}"
            : "=r"(done) : "r"(mb) : "memory");
        if (!done) {
            asm volatile(
                "{\n\t.reg .pred P1;\n\t"
                "WAIT_LOOP_%=:\n\t"
                "mbarrier.try_wait.parity.acquire.cta.shared::cta.b64 P1, [%0], 0, 0x989680;\n\t"
                "@P1 bra.uni WAIT_DONE_%=;\n\t"
                "bra.uni WAIT_LOOP_%=;\n\t"
                "WAIT_DONE_%=:\n\t}"
                :: "r"(mb) : "memory");
        }
    }

    if (tid < nv) {
        float la0 = s_la[3 * tid + 0], la1 = s_la[3 * tid + 1], la2 = s_la[3 * tid + 2];
        float vx = s_vt[3 * tid + 0] + 0.1f * tanha(la0);
        float vy = s_vt[3 * tid + 1] + 0.1f * tanha(la1);
        float vz = s_vt[3 * tid + 2] + 0.1f * tanha(la2);

        u64 acc0 = 0, acc1 = 0, acc2 = 0, acc3 = 0, acc4 = 0, acc5 = 0;
        const u64* cA2 = (const u64*)c_pack;
        const float* skv = &s_sk[tid * 23];
        #pragma unroll
        for (int j = 0; j < J; j++) {
            const u64 w2 = pack2(skv[j]);
            fma2(acc0, w2, cA2[6 * j + 0]);
            fma2(acc1, w2, cA2[6 * j + 1]);
            fma2(acc2, w2, cA2[6 * j + 2]);
            fma2(acc3, w2, cA2[6 * j + 3]);
            fma2(acc4, w2, cA2[6 * j + 4]);
            fma2(acc5, w2, cA2[6 * j + 5]);
        }

        float t0x, t0y, t0z, t0w, t1x, t1y, t1z, t1w, t2x, t2y, t2z, t2w;
        unpack2(acc0, t0x, t0y); unpack2(acc1, t0z, t0w);
        unpack2(acc2, t1x, t1y); unpack2(acc3, t1z, t1w);
        unpack2(acc4, t2x, t2y); unpack2(acc5, t2z, t2w);

        float x = fmaf(t0x, vx, fmaf(t0y, vy, fmaf(t0z, vz, t0w)));
        float y = fmaf(t1x, vx, fmaf(t1y, vy, fmaf(t1z, vz, t1w)));
        float z = fmaf(t2x, vx, fmaf(t2y, vy, fmaf(t2z, vz, t2w)));

        float c = c_pack[276];
        // overwrite own slots only -> no barrier needed before writes
        s_vt[3 * tid + 0] = fmaf(c, x, c_pack[277]);
        s_vt[3 * tid + 1] = fmaf(c, y, c_pack[278]);
        s_vt[3 * tid + 2] = fmaf(c, z, c_pack[279]);
    }
    __syncthreads();

    // cooperative vectorized streaming stores (B broadcast copies)
    {
        const float4* r4 = (const float4*)s_vt;
        const long stride4 = V3 >> 2;
        if (full) {
            if (tid < 192) {
                const float4 val = r4[tid];
                float4* go = (float4*)(out + v0 * 3);
                for (int b = 0; b < B; b++) {
                    __stcs(go + tid, val);
                    go += stride4;
                }
            }
        } else {
            const int n3 = (nv * 3) >> 2;
            float4* go = (float4*)(out + v0 * 3);
            for (int b = 0; b < B; b++) {
                for (int i = tid; i < n3; i += TPB) __stcs(go + i, r4[i]);
                go += stride4;
            }
        }
    }
}

extern "C" void kernel_launch(void* const* d_in, const int* in_sizes, int n_in,
                              void* d_out, int out_size)
{
    const float* vt    = (const float*)d_in[0];
    const float* sk    = (const float*)d_in[1];
    const float* jr    = (const float*)d_in[2];
    const float* p0    = (const float*)d_in[3];
    const float* p1    = (const float*)d_in[4];
    const float* p2    = (const float*)d_in[5];
    const float* p3    = (const float*)d_in[6];
    const float* p4    = (const float*)d_in[7];
    const float* p5    = (const float*)d_in[8];
    const float* p12   = (const float*)d_in[9];
    const float* p13   = (const float*)d_in[10];
    const float* la    = (const float*)d_in[11];
    const float* disp  = (const float*)d_in[12];
    const float* scale = (const float*)d_in[13];
    const float* loc   = (const float*)d_in[14];
    float* out = (float*)d_out;

    int V = in_sizes[0] / 3;
    long fixed = 69L + 69L + 1L + 3L + 3L * (long)V;
    int B = (int)(((long)out_size - fixed) / (3L * (long)V));

    static float* cpack_dev = nullptr;
    if (!cpack_dev) {
        void* p = nullptr;
        cudaGetSymbolAddress(&p, c_pack);
        cpack_dev = (float*)p;
    }

    prep_kernel<<<1, 32>>>(cpack_dev, jr, p0, p1, p2, p3, p4, p5, p12, p13,
                           disp, scale, loc, out, B, V);

    int blocks = (V + VPB - 1) / VPB;

    cudaLaunchConfig_t cfg = {};
    cfg.gridDim  = dim3(blocks, 1, 1);
    cfg.blockDim = dim3(TPB, 1, 1);
    cfg.dynamicSmemBytes = 0;
    cfg.stream = 0;
    cudaLaunchAttribute attrs[1];
    attrs[0].id = cudaLaunchAttributeProgrammaticStreamSerialization;
    attrs[0].val.programmaticStreamSerializationAllowed = 1;
    cfg.attrs = attrs;
    cfg.numAttrs = 1;
    cudaLaunchKernelEx(&cfg, lbs_kernel, vt, sk, la, out, V, B);
}

// round 15
// speedup vs baseline: 1.0063x; 1.0063x over previous
#include <cuda_runtime.h>
#include <math.h>

#define J   23
#define TPB 256
#define VPB 256
#define PI_F 3.14159265358979323846f

__constant__ int cPAR[J] = {-1,0,1,1,3,4,5,4,7,4,9,1,11,12,13,12,15,12,17,0,19,0,21};
// joints grouped by tree depth (level), offsets into cLVL
__constant__ int cLVL[J] = {0, 1,19,21, 2,3,11,20,22, 4,12, 5,7,9,13,15,17, 6,8,10,14,16,18};
__constant__ int cOFF[7] = {0, 1, 4, 9, 11, 17, 23};

// packed A (69 float4 = 276 floats) + constants (c, ox, oy, oz) at [276..279]
__constant__ __align__(16) float c_pack[280];

typedef unsigned long long u64;

__device__ __forceinline__ void fma2(u64& d, u64 a, u64 b) {
    asm("fma.rn.f32x2 %0, %1, %2, %0;" : "+l"(d) : "l"(a), "l"(b));
}
__device__ __forceinline__ u64 pack2(float v) {
    u64 r;
    asm("mov.b64 %0, {%1, %1};" : "=l"(r) : "f"(v));
    return r;
}
__device__ __forceinline__ void unpack2(u64 v, float& lo, float& hi) {
    asm("mov.b64 {%0, %1}, %2;" : "=f"(lo), "=f"(hi) : "l"(v));
}
__device__ __forceinline__ float tanha(float x) {
    float y;
    asm("tanh.approx.f32 %0, %1;" : "=f"(y) : "f"(x));
    return y;
}
__device__ __forceinline__ unsigned smem_u32(const void* p) {
    return (unsigned)__cvta_generic_to_shared(p);
}

// ---------------- Prep: 128 threads; level-parallel FK; writes constant bank; triggers PDL ----------------
__global__ void __launch_bounds__(128) prep_kernel(
    float* __restrict__ cpack,
    const float* __restrict__ jr,
    const float* __restrict__ p0, const float* __restrict__ p1,
    const float* __restrict__ p2, const float* __restrict__ p3,
    const float* __restrict__ p4, const float* __restrict__ p5,
    const float* __restrict__ p12, const float* __restrict__ p13,
    const float* __restrict__ disp, const float* __restrict__ scale,
    const float* __restrict__ loc,
    float* __restrict__ out, int B, int V)
{
    __shared__ float s_Tl[J * 12];
    __shared__ float s_G[J * 12];
    __shared__ float s_pose[J * 3];
    __shared__ float s_c4[4];

    const int tid = threadIdx.x;

    if (tid == 127) {
        float cst = 0.0035f * scale[0];
        float ox = loc[0] + 0.1f * tanha(disp[0]);
        float oy = loc[1] + 0.1f * tanha(disp[1]);
        float oz = loc[2] + 0.1f * tanha(disp[2]);
        cpack[276] = cst; cpack[277] = ox; cpack[278] = oy; cpack[279] = oz;
        s_c4[0] = cst; s_c4[1] = ox; s_c4[2] = oy; s_c4[3] = oz;
    }

    if (tid < J) {
        float fac = 0.f, sy = 1.f, sz = 1.f;
        const float* pp = p0;
        bool has = true;
        switch (tid) {
            case 0:  fac = PI_F / 2.f; pp = p0;  break;
            case 1:  fac = PI_F / 4.f; pp = p1;  break;
            case 2:  fac = PI_F / 9.f; pp = p2;  break;
            case 3:  fac = PI_F / 3.f; pp = p3;  break;
            case 4:  fac = PI_F / 3.f; pp = p4;  break;
            case 5:  fac = PI_F / 3.f; pp = p5;  break;
            case 11: fac = PI_F / 3.f; pp = p3;  sy = -1.f; sz = -1.f; break;
            case 12: fac = PI_F / 3.f; pp = p12; break;
            case 13: fac = PI_F / 3.f; pp = p13; break;
            default: has = false;
        }
        float px = 0.f, py = 0.f, pz = 0.f;
        if (has) {
            px = fac * tanha(pp[0]);
            py = sy * fac * tanha(pp[1]);
            pz = sz * fac * tanha(pp[2]);
        }
        s_pose[3 * tid + 0] = px;
        s_pose[3 * tid + 1] = py;
        s_pose[3 * tid + 2] = pz;

        float ang = sqrtf(px * px + py * py + pz * pz + 1e-12f);
        float inv = 1.f / ang;
        float x = px * inv, y = py * inv, z = pz * inv;
        float s = __sinf(ang), c = __cosf(ang), t = 1.f - c;
        float* T = &s_Tl[tid * 12];
        T[0] = 1.f + t * (-(z * z) - (y * y));
        T[1] = -s * z + t * (x * y);
        T[2] =  s * y + t * (x * z);
        T[4] =  s * z + t * (x * y);
        T[5] = 1.f + t * (-(z * z) - (x * x));
        T[6] = -s * x + t * (y * z);
        T[8] = -s * y + t * (x * z);
        T[9] =  s * x + t * (y * z);
        T[10] = 1.f + t * (-(y * y) - (x * x));

        int par = cPAR[tid];
        float jx = jr[3 * tid], jy = jr[3 * tid + 1], jz = jr[3 * tid + 2];
        if (par >= 0) { jx -= jr[3 * par]; jy -= jr[3 * par + 1]; jz -= jr[3 * par + 2]; }
        T[3] = jx; T[7] = jy; T[11] = jz;
    }
    __syncthreads();

    // Level 0: G[0] = Tl[0]
    if (tid < 12) s_G[tid] = s_Tl[tid];
    __syncthreads();

    // Levels 1..5: all joints of a level in parallel (≤6 joints × 12 elems = 72 threads)
    #pragma unroll
    for (int lv = 1; lv <= 5; lv++) {
        const int off = cOFF[lv];
        const int nj  = cOFF[lv + 1] - off;
        const int g   = tid / 12;
        if (g < nj) {
            const int e = tid - g * 12;
            const int j = cLVL[off + g];
            const int p = cPAR[j];
            const int r = e >> 2, c = e & 3;
            const float* gp = &s_G[p * 12 + r * 4];
            const float* tl = &s_Tl[j * 12];
            float v = gp[0] * tl[0 * 4 + c]
                    + gp[1] * tl[1 * 4 + c]
                    + gp[2] * tl[2 * 4 + c];
            if (c == 3) v += gp[3];
            s_G[j * 12 + e] = v;
        }
        __syncthreads();
    }

    if (tid < J) {
        const float* g = &s_G[tid * 12];
        float jx = jr[3 * tid], jy = jr[3 * tid + 1], jz = jr[3 * tid + 2];
        float tcx = g[0] * jx + g[1] * jy + g[2] * jz;
        float tcy = g[4] * jx + g[5] * jy + g[6] * jz;
        float tcz = g[8] * jx + g[9] * jy + g[10] * jz;
        float* a = &cpack[tid * 12];
        a[0] = g[0]; a[1] = g[1]; a[2]  = g[2];  a[3]  = g[3]  - tcx;
        a[4] = g[4]; a[5] = g[5]; a[6]  = g[6];  a[7]  = g[7]  - tcy;
        a[8] = g[8]; a[9] = g[9]; a[10] = g[10]; a[11] = g[11] - tcz;
    }
    __syncthreads();
    if (tid == 0) __threadfence();
    __syncthreads();
    cudaTriggerProgrammaticLaunchCompletion();

    // small outputs (after trigger; off the lbs critical path)
    const long V3 = 3L * (long)V;
    const long base = (long)B * V3;
    if (tid < J) {
        float cst = s_c4[0];
        out[base + 3 * tid + 0] = s_pose[3 * tid + 0];
        out[base + 3 * tid + 1] = s_pose[3 * tid + 1];
        out[base + 3 * tid + 2] = s_pose[3 * tid + 2];
        out[base + 69 + 3 * tid + 0] = fmaf(cst, s_G[tid * 12 + 3],  s_c4[1]);
        out[base + 69 + 3 * tid + 1] = fmaf(cst, s_G[tid * 12 + 7],  s_c4[2]);
        out[base + 69 + 3 * tid + 2] = fmaf(cst, s_G[tid * 12 + 11], s_c4[3]);
    }
    if (tid == 127) {
        out[base + 138] = scale[0];
        out[base + 139] = disp[0];
        out[base + 140] = disp[1];
        out[base + 141] = disp[2];
    }
}

// ---------------- LBS: TMA sk staging, PDL preamble, constant-bank A, f32x2 ----------------
__global__ void __launch_bounds__(TPB, 6) lbs_kernel(
    const float* __restrict__ vt,
    const float* __restrict__ sk,
    const float* __restrict__ la,
    float* __restrict__ out, int V, int B)
{
    __shared__ __align__(16) float s_sk[VPB * 23];
    __shared__ float s_vt[VPB * 3];    // reused for results after compute
    __shared__ float s_la[VPB * 3];
    __shared__ __align__(8) u64 s_mbar;

    const int tid = threadIdx.x;
    const long v0 = (long)blockIdx.x * VPB;
    const int nv  = (V - (int)v0 < VPB) ? (V - (int)v0) : VPB;
    const long V3 = 3L * (long)V;
    const bool full = (nv == VPB);
    const long offLa = (long)B * V3 + 142;

    // ---- PDL preamble (independent of prep) ----
    if (tid == 0) {
        const unsigned mb = smem_u32(&s_mbar);
        const unsigned dst = smem_u32(s_sk);
        const unsigned bytes = (unsigned)(nv * 23 * 4);   // multiple of 16
        const void* src = (const void*)(sk + v0 * 23);
        asm volatile("mbarrier.init.shared.b64 [%0], 1;" :: "r"(mb) : "memory");
        asm volatile("mbarrier.arrive.expect_tx.shared.b64 _, [%0], %1;"
                     :: "r"(mb), "r"(bytes) : "memory");
        asm volatile("cp.async.bulk.shared::cta.global.mbarrier::complete_tx::bytes "
                     "[%0], [%1], %2, [%3];"
                     :: "r"(dst), "l"(src), "r"(bytes), "r"(mb) : "memory");
    }

    {
        const float4* gv = (const float4*)(vt + v0 * 3);
        const float4* gl = (const float4*)(la + v0 * 3);
        float4* dv = (float4*)s_vt;
        float4* dl = (float4*)s_la;
        float2* gl2 = (float2*)(out + offLa + v0 * 3);
        if (full) {
            if (tid < 192) {
                dv[tid] = __ldcs(gv + tid);
                float4 lq = __ldcs(gl + tid);
                dl[tid] = lq;
                __stcs(gl2 + 2 * tid + 0, make_float2(lq.x, lq.y));
                __stcs(gl2 + 2 * tid + 1, make_float2(lq.z, lq.w));
            }
        } else {
            const int n3 = (nv * 3) >> 2;
            for (int i = tid; i < n3; i += TPB) {
                dv[i] = __ldcs(gv + i);
                float4 lq = __ldcs(gl + i);
                dl[i] = lq;
                __stcs(gl2 + 2 * i + 0, make_float2(lq.x, lq.y));
                __stcs(gl2 + 2 * i + 1, make_float2(lq.z, lq.w));
            }
        }
    }

    __syncthreads();   // vt/la smem + mbar init visible

    // vh from smem (no dependency on prep or TMA)
    float vx = 0.f, vy = 0.f, vz = 0.f;
    if (tid < nv) {
        vx = s_vt[3 * tid + 0] + 0.1f * tanha(s_la[3 * tid + 0]);
        vy = s_vt[3 * tid + 1] + 0.1f * tanha(s_la[3 * tid + 1]);
        vz = s_vt[3 * tid + 2] + 0.1f * tanha(s_la[3 * tid + 2]);
    }

    cudaGridDependencySynchronize();   // prep's c_pack ready

    // wait for the TMA bulk copy
    {
        const unsigned mb = smem_u32(&s_mbar);
        unsigned done;
        asm volatile(
            "{\n\t.reg .pred p;\n\t"
            "mbarrier.try_wait.parity.acquire.cta.shared::cta.b64 p, [%1], 0;\n\t"
            "selp.b32 %0, 1, 0, p;\n\t}"
            : "=r"(done) : "r"(mb) : "memory");
        if (!done) {
            asm volatile(
                "{\n\t.reg .pred P1;\n\t"
                "WAIT_LOOP_%=:\n\t"
                "mbarrier.try_wait.parity.acquire.cta.shared::cta.b64 P1, [%0], 0, 0x989680;\n\t"
                "@P1 bra.uni WAIT_DONE_%=;\n\t"
                "bra.uni WAIT_LOOP_%=;\n\t"
                "WAIT_DONE_%=:\n\t}"
                :: "r"(mb) : "memory");
        }
    }

    if (tid < nv) {
        u64 acc0 = 0, acc1 = 0, acc2 = 0, acc3 = 0, acc4 = 0, acc5 = 0;
        const u64* cA2 = (const u64*)c_pack;
        const float* skv = &s_sk[tid * 23];
        #pragma unroll
        for (int j = 0; j < J; j++) {
            const u64 w2 = pack2(skv[j]);
            fma2(acc0, w2, cA2[6 * j + 0]);
            fma2(acc1, w2, cA2[6 * j + 1]);
            fma2(acc2, w2, cA2[6 * j + 2]);
            fma2(acc3, w2, cA2[6 * j + 3]);
            fma2(acc4, w2, cA2[6 * j + 4]);
            fma2(acc5, w2, cA2[6 * j + 5]);
        }

        float t0x, t0y, t0z, t0w, t1x, t1y, t1z, t1w, t2x, t2y, t2z, t2w;
        unpack2(acc0, t0x, t0y); unpack2(acc1, t0z, t0w);
        unpack2(acc2, t1x, t1y); unpack2(acc3, t1z, t1w);
        unpack2(acc4, t2x, t2y); unpack2(acc5, t2z, t2w);

        float x = fmaf(t0x, vx, fmaf(t0y, vy, fmaf(t0z, vz, t0w)));
        float y = fmaf(t1x, vx, fmaf(t1y, vy, fmaf(t1z, vz, t1w)));
        float z = fmaf(t2x, vx, fmaf(t2y, vy, fmaf(t2z, vz, t2w)));

        float c = c_pack[276];
        // overwrite own slots only -> no barrier needed before writes
        s_vt[3 * tid + 0] = fmaf(c, x, c_pack[277]);
        s_vt[3 * tid + 1] = fmaf(c, y, c_pack[278]);
        s_vt[3 * tid + 2] = fmaf(c, z, c_pack[279]);
    }
    __syncthreads();

    // cooperative vectorized streaming stores (B broadcast copies)
    {
        const float4* r4 = (const float4*)s_vt;
        const long stride4 = V3 >> 2;
        if (full) {
            if (tid < 192) {
                const float4 val = r4[tid];
                float4* go = (float4*)(out + v0 * 3);
                for (int b = 0; b < B; b++) {
                    __stcs(go + tid, val);
                    go += stride4;
                }
            }
        } else {
            const int n3 = (nv * 3) >> 2;
            float4* go = (float4*)(out + v0 * 3);
            for (int b = 0; b < B; b++) {
                for (int i = tid; i < n3; i += TPB) __stcs(go + i, r4[i]);
                go += stride4;
            }
        }
    }
}

extern "C" void kernel_launch(void* const* d_in, const int* in_sizes, int n_in,
                              void* d_out, int out_size)
{
    const float* vt    = (const float*)d_in[0];
    const float* sk    = (const float*)d_in[1];
    const float* jr    = (const float*)d_in[2];
    const float* p0    = (const float*)d_in[3];
    const float* p1    = (const float*)d_in[4];
    const float* p2    = (const float*)d_in[5];
    const float* p3    = (const float*)d_in[6];
    const float* p4    = (const float*)d_in[7];
    const float* p5    = (const float*)d_in[8];
    const float* p12   = (const float*)d_in[9];
    const float* p13   = (const float*)d_in[10];
    const float* la    = (const float*)d_in[11];
    const float* disp  = (const float*)d_in[12];
    const float* scale = (const float*)d_in[13];
    const float* loc   = (const float*)d_in[14];
    float* out = (float*)d_out;

    int V = in_sizes[0] / 3;
    long fixed = 69L + 69L + 1L + 3L + 3L * (long)V;
    int B = (int)(((long)out_size - fixed) / (3L * (long)V));

    static float* cpack_dev = nullptr;
    if (!cpack_dev) {
        void* p = nullptr;
        cudaGetSymbolAddress(&p, c_pack);
        cpack_dev = (float*)p;
    }

    prep_kernel<<<1, 128>>>(cpack_dev, jr, p0, p1, p2, p3, p4, p5, p12, p13,
                            disp, scale, loc, out, B, V);

    int blocks = (V + VPB - 1) / VPB;

    cudaLaunchConfig_t cfg = {};
    cfg.gridDim  = dim3(blocks, 1, 1);
    cfg.blockDim = dim3(TPB, 1, 1);
    cfg.dynamicSmemBytes = 0;
    cfg.stream = 0;
    cudaLaunchAttribute attrs[1];
    attrs[0].id = cudaLaunchAttributeProgrammaticStreamSerialization;
    attrs[0].val.programmaticStreamSerializationAllowed = 1;
    cfg.attrs = attrs;
    cfg.numAttrs = 1;
    cudaLaunchKernelEx(&cfg, lbs_kernel, vt, sk, la, out, V, B);
}